// round 10
// baseline (speedup 1.0000x reference)
#include <cuda_runtime.h>
#include <cuda_bf16.h>

typedef __nv_bfloat16 bf16;

// ---------------------------------------------------------------------------
// StDimLocalLocalContrastModel via mma.sync bf16 (split-2 emulated fp32).
//   P=64, B=1024, C=256, HID=512, M = B*P = 65536
// GEMM1 (standalone) -> fused GEMM2+GEMM3 (aprime stays in smem) -> GEMM4 -> rowmax
// ---------------------------------------------------------------------------

#define BM 128
#define BN 128
#define BKK 32
#define TILE_ELEMS 4096               // 128 rows x 32 bf16 = 8 KB
#define NSTAGE 3
#define SMEM_BYTES (4 * NSTAGE * TILE_ELEMS * 2)   // 96 KB (mma_gemm)

// fused kernel smem layout (bf16 elem offsets)
#define F_AP   0                      // aprime hi 64x256
#define F_APL  16384                  // aprime lo
#define F_STG  32768                  // stage region
#define F_SS   20480                  // stage stride: Ah 2048|Al 2048|Bh 8192|Bl 8192
#define F_SMEM_BYTES ((32768 + 3 * F_SS) * 2)      // 188416 B

// ---- scratch (device globals; allocation-free) ----
__device__ bf16 g_a_hi  [16777216];   // [65536,256] anchor -> later pred (alias)
__device__ bf16 g_a_lo  [16777216];
__device__ bf16 g_pos_hi[16777216];   // [65536,256]
__device__ bf16 g_pos_lo[16777216];
__device__ bf16 g_hid_hi[33554432];   // [65536,512]
__device__ bf16 g_hid_lo[33554432];
__device__ bf16 g_w1_hi [131072], g_w1_lo[131072];   // [512,256]
__device__ bf16 g_w2_hi [131072], g_w2_lo[131072];   // [256,512]
__device__ bf16 g_ww_hi [65536],  g_ww_lo[65536];    // [256,256]

// ---- PTX helpers ----
__device__ __forceinline__ void cp16(const bf16* src, bf16* dst) {
    unsigned d = (unsigned)__cvta_generic_to_shared(dst);
    asm volatile("cp.async.cg.shared.global [%0], [%1], 16;" :: "r"(d), "l"(src));
}
__device__ __forceinline__ void cp_commit() { asm volatile("cp.async.commit_group;"); }
template<int N> __device__ __forceinline__ void cp_wait() {
    asm volatile("cp.async.wait_group %0;" :: "n"(N));
}
__device__ __forceinline__ void ldsm4(unsigned* r, const bf16* p) {
    unsigned a = (unsigned)__cvta_generic_to_shared(p);
    asm volatile("ldmatrix.sync.aligned.m8n8.x4.shared.b16 {%0,%1,%2,%3}, [%4];"
        : "=r"(r[0]), "=r"(r[1]), "=r"(r[2]), "=r"(r[3]) : "r"(a));
}
__device__ __forceinline__ void mma_bf16(float* d, const unsigned* a, const unsigned* b) {
    asm volatile(
        "mma.sync.aligned.m16n8k16.row.col.f32.bf16.bf16.f32 "
        "{%0,%1,%2,%3}, {%4,%5,%6,%7}, {%8,%9}, {%0,%1,%2,%3};"
        : "+f"(d[0]), "+f"(d[1]), "+f"(d[2]), "+f"(d[3])
        : "r"(a[0]), "r"(a[1]), "r"(a[2]), "r"(a[3]), "r"(b[0]), "r"(b[1]));
}

// swizzle for 32-elem-wide stage tiles: chunk' = chunk ^ ((row>>1)&3)
__device__ __forceinline__ const bf16* swz(const bf16* tile, int row, int kcol) {
    return tile + row * 32 + ((((kcol >> 3)) ^ ((row >> 1) & 3)) << 3);
}
// swizzle for 256-elem-wide resident aprime tile: chunk' = chunk ^ (row&7)
__device__ __forceinline__ const bf16* swz256(const bf16* tile, int row, int kcol) {
    return tile + row * 256 + ((((kcol >> 3)) ^ (row & 7)) << 3);
}

// ---------------------------------------------------------------------------
// mma_gemm (unchanged from R9): CTA 128x128, 3-stage, 2 CTAs/SM.
// MODE 0: fp32 out   MODE 1: relu(acc+bias)->hi/lo
// ---------------------------------------------------------------------------
template<int MODE>
__global__ __launch_bounds__(256, 2)
void mma_gemm(const bf16* __restrict__ Ahi, const bf16* __restrict__ Alo, long As, long Ab,
              const bf16* __restrict__ Bhi, const bf16* __restrict__ Blo, long Bs, long Bb,
              int K,
              float* __restrict__ Cf, long Cs, long Cb,
              bf16* __restrict__ Ohi, bf16* __restrict__ Olo, long Os,
              const float* __restrict__ bias)
{
    extern __shared__ bf16 smem[];
    bf16* sAh = smem;
    bf16* sAl = smem + NSTAGE * TILE_ELEMS;
    bf16* sBh = smem + 2 * NSTAGE * TILE_ELEMS;
    bf16* sBl = smem + 3 * NSTAGE * TILE_ELEMS;

    const int tid = threadIdx.x;
    const int wid = tid >> 5;
    const int lane = tid & 31;
    const long z = blockIdx.z;

    const bf16* gAh = Ahi + z * Ab + (long)blockIdx.y * BM * As;
    const bf16* gAl = Alo + z * Ab + (long)blockIdx.y * BM * As;
    const bf16* gBh = Bhi + z * Bb + (long)blockIdx.x * BN * Bs;
    const bf16* gBl = Blo + z * Bb + (long)blockIdx.x * BN * Bs;

    auto loadTile = [&](const bf16* g, long stride, int k0, bf16* dst) {
        #pragma unroll
        for (int it = 0; it < 2; it++) {
            int c = tid + it * 256;
            int r = c >> 2, kc = c & 3;
            cp16(g + (long)r * stride + k0 + kc * 8,
                 dst + r * 32 + ((kc ^ ((r >> 1) & 3)) << 3));
        }
    };
    auto loadAll = [&](int kt, int s) {
        int k0 = kt * BKK;
        loadTile(gAh, As, k0, sAh + s * TILE_ELEMS);
        loadTile(gAl, As, k0, sAl + s * TILE_ELEMS);
        loadTile(gBh, Bs, k0, sBh + s * TILE_ELEMS);
        loadTile(gBl, Bs, k0, sBl + s * TILE_ELEMS);
        cp_commit();
    };

    float acc[4][4][4];
    #pragma unroll
    for (int i = 0; i < 4; i++)
        #pragma unroll
        for (int j = 0; j < 4; j++)
            #pragma unroll
            for (int q = 0; q < 4; q++) acc[i][j][q] = 0.0f;

    const int wm = (wid >> 2) * 64;
    const int wn = (wid & 3) * 32;
    const int aRow = (lane & 7) + ((lane >> 3) & 1) * 8;
    const int aColH = ((lane >> 4) & 1) * 8;
    const int bRow = (lane & 7) + ((lane >> 4) & 1) * 8;
    const int bColH = ((lane >> 3) & 1) * 8;

    const int nk = K / BKK;
    loadAll(0, 0);
    loadAll(1, 1);

    for (int kt = 0; kt < nk; kt++) {
        if (kt + 1 < nk) cp_wait<1>(); else cp_wait<0>();
        __syncthreads();
        if (kt + 2 < nk) loadAll(kt + 2, (kt + 2) % NSTAGE);

        const int s = kt % NSTAGE;
        const bf16* Ah = sAh + s * TILE_ELEMS;
        const bf16* Al = sAl + s * TILE_ELEMS;
        const bf16* Bh = sBh + s * TILE_ELEMS;
        const bf16* Bl = sBl + s * TILE_ELEMS;

        #pragma unroll
        for (int kh = 0; kh < BKK; kh += 16) {
            unsigned Bh4[2][4], Bl4[2][4];
            #pragma unroll
            for (int nj = 0; nj < 2; nj++) {
                ldsm4(Bh4[nj], swz(Bh, wn + nj * 16 + bRow, kh + bColH));
                ldsm4(Bl4[nj], swz(Bl, wn + nj * 16 + bRow, kh + bColH));
            }
            #pragma unroll
            for (int mi = 0; mi < 4; mi++) {
                unsigned Ah4[4], Al4[4];
                ldsm4(Ah4, swz(Ah, wm + mi * 16 + aRow, kh + aColH));
                ldsm4(Al4, swz(Al, wm + mi * 16 + aRow, kh + aColH));
                #pragma unroll
                for (int ni = 0; ni < 4; ni++) {
                    const unsigned* bh = &Bh4[ni >> 1][(ni & 1) * 2];
                    const unsigned* bl = &Bl4[ni >> 1][(ni & 1) * 2];
                    mma_bf16(acc[mi][ni], Ah4, bh);
                    mma_bf16(acc[mi][ni], Ah4, bl);
                    mma_bf16(acc[mi][ni], Al4, bh);
                }
            }
        }
    }

    const int quad = lane >> 2, qt = lane & 3;
    const long rowBase = (long)blockIdx.y * BM + wm;
    const int colBase = blockIdx.x * BN + wn;

    #pragma unroll
    for (int mi = 0; mi < 4; mi++) {
        #pragma unroll
        for (int ni = 0; ni < 4; ni++) {
            #pragma unroll
            for (int half = 0; half < 2; half++) {
                long m = rowBase + mi * 16 + quad + half * 8;
                int n = colBase + ni * 8 + qt * 2;
                float v0 = acc[mi][ni][half * 2 + 0];
                float v1 = acc[mi][ni][half * 2 + 1];
                if (MODE == 0) {
                    *(float2*)(Cf + z * Cb + m * Cs + n) = make_float2(v0, v1);
                } else {
                    v0 = fmaxf(v0 + bias[n], 0.0f);
                    v1 = fmaxf(v1 + bias[n + 1], 0.0f);
                    bf16 h0 = __float2bfloat16(v0);
                    bf16 h1 = __float2bfloat16(v1);
                    bf16 l0 = __float2bfloat16(v0 - __bfloat162float(h0));
                    bf16 l1 = __float2bfloat16(v1 - __bfloat162float(h1));
                    __nv_bfloat162 hp; hp.x = h0; hp.y = h1;
                    __nv_bfloat162 lp; lp.x = l0; lp.y = l1;
                    *(__nv_bfloat162*)(Ohi + m * Os + n) = hp;
                    *(__nv_bfloat162*)(Olo + m * Os + n) = lp;
                }
            }
        }
    }
}

// ---------------------------------------------------------------------------
// fused GEMM2+GEMM3: CTA = 64 rows x 256 cols (full C).
// Phase 1: aprime = hidden @ W2^T + b2 + resid  -> smem (hi/lo, swizzled)
// Phase 2: pred   = aprime @ Ww^T               -> gmem hi/lo
// 8 warps (2M x 4N), warp tile 32x64.  occ 1 (184 KB smem).
// ---------------------------------------------------------------------------
__global__ __launch_bounds__(256, 1)
void fused_mlp(const bf16* __restrict__ hh, const bf16* __restrict__ hl,
               const bf16* __restrict__ w2h, const bf16* __restrict__ w2l,
               const bf16* __restrict__ wwh, const bf16* __restrict__ wwl,
               const float* __restrict__ b2,
               const bf16* __restrict__ rh, const bf16* __restrict__ rl,
               bf16* __restrict__ oh, bf16* __restrict__ ol)
{
    extern __shared__ bf16 smem[];
    const int tid = threadIdx.x;
    const int wid = tid >> 5;
    const int lane = tid & 31;
    const long m0 = (long)blockIdx.x * 64;

    const int wm = (wid >> 2) * 32;      // 2 M-warps
    const int wn = (wid & 3) * 64;       // 4 N-warps, warp tile 32x64
    const int aRow = (lane & 7) + ((lane >> 3) & 1) * 8;
    const int aColH = ((lane >> 4) & 1) * 8;
    const int bRow = (lane & 7) + ((lane >> 4) & 1) * 8;
    const int bColH = ((lane >> 3) & 1) * 8;
    const int quad = lane >> 2, qt = lane & 3;

    // phase-1 loader: A = hidden 64x32, B = W2 256x32 (both hi+lo)
    auto load1 = [&](int kt, int s) {
        int k0 = kt * 32;
        bf16* base = smem + F_STG + s * F_SS;
        {
            int r = tid >> 2, kc = tid & 3;
            bf16* d = base + r * 32 + ((kc ^ ((r >> 1) & 3)) << 3);
            cp16(hh + (m0 + r) * 512 + k0 + kc * 8, d);
            cp16(hl + (m0 + r) * 512 + k0 + kc * 8, d + 2048);
        }
        #pragma unroll
        for (int it = 0; it < 4; it++) {
            int c = tid + it * 256;
            int r = c >> 2, kc = c & 3;
            bf16* d = base + 4096 + r * 32 + ((kc ^ ((r >> 1) & 3)) << 3);
            cp16(w2h + (long)r * 512 + k0 + kc * 8, d);
            cp16(w2l + (long)r * 512 + k0 + kc * 8, d + 8192);
        }
        cp_commit();
    };
    // phase-2 loader: B = Ww 256x32 (A resident in smem)
    auto load2 = [&](int kt, int s) {
        int k0 = kt * 32;
        bf16* base = smem + F_STG + s * F_SS;
        #pragma unroll
        for (int it = 0; it < 4; it++) {
            int c = tid + it * 256;
            int r = c >> 2, kc = c & 3;
            bf16* d = base + 4096 + r * 32 + ((kc ^ ((r >> 1) & 3)) << 3);
            cp16(wwh + (long)r * 256 + k0 + kc * 8, d);
            cp16(wwl + (long)r * 256 + k0 + kc * 8, d + 8192);
        }
        cp_commit();
    };

    float acc[2][8][4];
    #pragma unroll
    for (int i = 0; i < 2; i++)
        #pragma unroll
        for (int j = 0; j < 8; j++)
            #pragma unroll
            for (int q = 0; q < 4; q++) acc[i][j][q] = 0.0f;

    // ---- phase 1: K = 512 (16 k-tiles), 3-stage ----
    load1(0, 0);
    load1(1, 1);
    for (int kt = 0; kt < 16; kt++) {
        if (kt + 1 < 16) cp_wait<1>(); else cp_wait<0>();
        __syncthreads();
        if (kt + 2 < 16) load1(kt + 2, (kt + 2) % NSTAGE);

        bf16* base = smem + F_STG + (kt % NSTAGE) * F_SS;
        const bf16* Ah = base;
        const bf16* Al = base + 2048;
        const bf16* Bh = base + 4096;
        const bf16* Bl = base + 12288;

        #pragma unroll
        for (int kh = 0; kh < 32; kh += 16) {
            unsigned Bh4[4][4], Bl4[4][4];
            #pragma unroll
            for (int nj = 0; nj < 4; nj++) {
                ldsm4(Bh4[nj], swz(Bh, wn + nj * 16 + bRow, kh + bColH));
                ldsm4(Bl4[nj], swz(Bl, wn + nj * 16 + bRow, kh + bColH));
            }
            #pragma unroll
            for (int mi = 0; mi < 2; mi++) {
                unsigned Ah4[4], Al4[4];
                ldsm4(Ah4, swz(Ah, wm + mi * 16 + aRow, kh + aColH));
                ldsm4(Al4, swz(Al, wm + mi * 16 + aRow, kh + aColH));
                #pragma unroll
                for (int ni = 0; ni < 8; ni++) {
                    const unsigned* bh = &Bh4[ni >> 1][(ni & 1) * 2];
                    const unsigned* bl = &Bl4[ni >> 1][(ni & 1) * 2];
                    mma_bf16(acc[mi][ni], Ah4, bh);
                    mma_bf16(acc[mi][ni], Ah4, bl);
                    mma_bf16(acc[mi][ni], Al4, bh);
                }
            }
        }
    }

    // ---- phase-1 epilogue: + b2 + residual -> hi/lo into smem aprime ----
    #pragma unroll
    for (int mi = 0; mi < 2; mi++) {
        #pragma unroll
        for (int ni = 0; ni < 8; ni++) {
            #pragma unroll
            for (int half = 0; half < 2; half++) {
                int m = wm + mi * 16 + quad + half * 8;
                int n = wn + ni * 8 + qt * 2;
                long gm = m0 + m;
                __nv_bfloat162 rhv = *(const __nv_bfloat162*)(rh + gm * 256 + n);
                __nv_bfloat162 rlv = *(const __nv_bfloat162*)(rl + gm * 256 + n);
                float v0 = acc[mi][ni][half * 2 + 0] + b2[n]
                         + __bfloat162float(rhv.x) + __bfloat162float(rlv.x);
                float v1 = acc[mi][ni][half * 2 + 1] + b2[n + 1]
                         + __bfloat162float(rhv.y) + __bfloat162float(rlv.y);
                bf16 h0 = __float2bfloat16(v0);
                bf16 h1 = __float2bfloat16(v1);
                bf16 l0 = __float2bfloat16(v0 - __bfloat162float(h0));
                bf16 l1 = __float2bfloat16(v1 - __bfloat162float(h1));
                int off = m * 256 + ((((n >> 3)) ^ (m & 7)) << 3) + (n & 7);
                __nv_bfloat162 hp; hp.x = h0; hp.y = h1;
                __nv_bfloat162 lp; lp.x = l0; lp.y = l1;
                *(__nv_bfloat162*)(smem + F_AP + off)  = hp;
                *(__nv_bfloat162*)(smem + F_APL + off) = lp;
                acc[mi][ni][half * 2 + 0] = 0.0f;
                acc[mi][ni][half * 2 + 1] = 0.0f;
            }
        }
    }
    __syncthreads();

    // ---- phase 2: pred = aprime @ Ww^T, K = 256 (8 k-tiles) ----
    load2(0, 0);
    load2(1, 1);
    for (int kt = 0; kt < 8; kt++) {
        if (kt + 1 < 8) cp_wait<1>(); else cp_wait<0>();
        __syncthreads();
        if (kt + 2 < 8) load2(kt + 2, (kt + 2) % NSTAGE);

        bf16* base = smem + F_STG + (kt % NSTAGE) * F_SS;
        const bf16* Bh = base + 4096;
        const bf16* Bl = base + 12288;

        #pragma unroll
        for (int kh = 0; kh < 32; kh += 16) {
            unsigned Bh4[4][4], Bl4[4][4];
            #pragma unroll
            for (int nj = 0; nj < 4; nj++) {
                ldsm4(Bh4[nj], swz(Bh, wn + nj * 16 + bRow, kh + bColH));
                ldsm4(Bl4[nj], swz(Bl, wn + nj * 16 + bRow, kh + bColH));
            }
            #pragma unroll
            for (int mi = 0; mi < 2; mi++) {
                int row = wm + mi * 16 + aRow;
                int kcol = kt * 32 + kh + aColH;
                unsigned Ah4[4], Al4[4];
                ldsm4(Ah4, swz256(smem + F_AP, row, kcol));
                ldsm4(Al4, swz256(smem + F_APL, row, kcol));
                #pragma unroll
                for (int ni = 0; ni < 8; ni++) {
                    const unsigned* bh = &Bh4[ni >> 1][(ni & 1) * 2];
                    const unsigned* bl = &Bl4[ni >> 1][(ni & 1) * 2];
                    mma_bf16(acc[mi][ni], Ah4, bh);
                    mma_bf16(acc[mi][ni], Ah4, bl);
                    mma_bf16(acc[mi][ni], Al4, bh);
                }
            }
        }
    }

    // ---- phase-2 epilogue: pred hi/lo -> gmem ----
    #pragma unroll
    for (int mi = 0; mi < 2; mi++) {
        #pragma unroll
        for (int ni = 0; ni < 8; ni++) {
            #pragma unroll
            for (int half = 0; half < 2; half++) {
                int m = wm + mi * 16 + quad + half * 8;
                int n = wn + ni * 8 + qt * 2;
                long gm = m0 + m;
                float v0 = acc[mi][ni][half * 2 + 0];
                float v1 = acc[mi][ni][half * 2 + 1];
                bf16 h0 = __float2bfloat16(v0);
                bf16 h1 = __float2bfloat16(v1);
                bf16 l0 = __float2bfloat16(v0 - __bfloat162float(h0));
                bf16 l1 = __float2bfloat16(v1 - __bfloat162float(h1));
                __nv_bfloat162 hp; hp.x = h0; hp.y = h1;
                __nv_bfloat162 lp; lp.x = l0; lp.y = l1;
                *(__nv_bfloat162*)(oh + gm * 256 + n) = hp;
                *(__nv_bfloat162*)(ol + gm * 256 + n) = lp;
            }
        }
    }
}

// ---------------------------------------------------------------------------
// prep: [1024][256][64] fp32 -> hi/lo bf16 [(b*64+p)][c]
// ---------------------------------------------------------------------------
__global__ void transpose_split(const float* __restrict__ in0, bf16* __restrict__ h0, bf16* __restrict__ l0,
                                const float* __restrict__ in1, bf16* __restrict__ h1, bf16* __restrict__ l1) {
    __shared__ float t[32][33];
    const float* in = blockIdx.z ? in1 : in0;
    bf16* oh = blockIdx.z ? h1 : h0;
    bf16* ol = blockIdx.z ? l1 : l0;
    int b  = blockIdx.y;
    int c0 = (blockIdx.x & 7) * 32;
    int p0 = (blockIdx.x >> 3) * 32;
    const float* src = in + (long)b * 16384;
    #pragma unroll
    for (int j = 0; j < 32; j += 8)
        t[threadIdx.y + j][threadIdx.x] = src[(c0 + threadIdx.y + j) * 64 + p0 + threadIdx.x];
    __syncthreads();
    #pragma unroll
    for (int j = 0; j < 32; j += 8) {
        float v = t[threadIdx.x][threadIdx.y + j];
        long rowoff = ((long)b * 64 + p0 + threadIdx.y + j) * 256 + c0 + threadIdx.x;
        bf16 h = __float2bfloat16(v);
        oh[rowoff] = h;
        ol[rowoff] = __float2bfloat16(v - __bfloat162float(h));
    }
}

// all three weight splits in one launch: W1 (131072) | W2 (131072) | Ww (65536)
__global__ void split_w3(const float* __restrict__ W1, bf16* __restrict__ w1h, bf16* __restrict__ w1l,
                         const float* __restrict__ W2, bf16* __restrict__ w2h, bf16* __restrict__ w2l,
                         const float* __restrict__ Ww, bf16* __restrict__ wwh, bf16* __restrict__ wwl) {
    int i = blockIdx.x * 256 + threadIdx.x;
    const float* w; bf16 *hi, *lo; int off;
    if (i < 131072)      { w = W1; hi = w1h; lo = w1l; off = i; }
    else if (i < 262144) { w = W2; hi = w2h; lo = w2l; off = i - 131072; }
    else                 { w = Ww; hi = wwh; lo = wwl; off = i - 262144; }
    float v = w[off];
    bf16 h = __float2bfloat16(v);
    hi[off] = h;
    lo[off] = __float2bfloat16(v - __bfloat162float(h));
}

// subtract row max in-place, row = 1024 floats
__global__ void rowmax_kernel(float* __restrict__ out) {
    long row = blockIdx.x;
    float4* rp = (float4*)(out + row * 1024);
    float4 v = rp[threadIdx.x];
    float m = fmaxf(fmaxf(v.x, v.y), fmaxf(v.z, v.w));
    #pragma unroll
    for (int o = 16; o; o >>= 1) m = fmaxf(m, __shfl_xor_sync(0xffffffffu, m, o));
    __shared__ float sm[8];
    if ((threadIdx.x & 31) == 0) sm[threadIdx.x >> 5] = m;
    __syncthreads();
    float mm = sm[0];
    #pragma unroll
    for (int i = 1; i < 8; i++) mm = fmaxf(mm, sm[i]);
    v.x -= mm; v.y -= mm; v.z -= mm; v.w -= mm;
    rp[threadIdx.x] = v;
}

extern "C" void kernel_launch(void* const* d_in, const int* in_sizes, int n_in,
                              void* d_out, int out_size) {
    const float* anchor   = (const float*)d_in[0];
    const float* positive = (const float*)d_in[1];
    const float* W1 = (const float*)d_in[2];
    const float* b1 = (const float*)d_in[3];
    const float* W2 = (const float*)d_in[4];
    const float* b2 = (const float*)d_in[5];
    const float* Ww = (const float*)d_in[6];
    float* out = (float*)d_out;

    bf16 *ah, *al, *ph, *pl, *hh, *hl;
    bf16 *w1h, *w1l, *w2h, *w2l, *wwh, *wwl;
    cudaGetSymbolAddress((void**)&ah,  g_a_hi);
    cudaGetSymbolAddress((void**)&al,  g_a_lo);
    cudaGetSymbolAddress((void**)&ph,  g_pos_hi);
    cudaGetSymbolAddress((void**)&pl,  g_pos_lo);
    cudaGetSymbolAddress((void**)&hh,  g_hid_hi);
    cudaGetSymbolAddress((void**)&hl,  g_hid_lo);
    cudaGetSymbolAddress((void**)&w1h, g_w1_hi);
    cudaGetSymbolAddress((void**)&w1l, g_w1_lo);
    cudaGetSymbolAddress((void**)&w2h, g_w2_hi);
    cudaGetSymbolAddress((void**)&w2l, g_w2_lo);
    cudaGetSymbolAddress((void**)&wwh, g_ww_hi);
    cudaGetSymbolAddress((void**)&wwl, g_ww_lo);

    cudaFuncSetAttribute(mma_gemm<0>, cudaFuncAttributeMaxDynamicSharedMemorySize, SMEM_BYTES);
    cudaFuncSetAttribute(mma_gemm<1>, cudaFuncAttributeMaxDynamicSharedMemorySize, SMEM_BYTES);
    cudaFuncSetAttribute(fused_mlp,   cudaFuncAttributeMaxDynamicSharedMemorySize, F_SMEM_BYTES);

    // prep
    transpose_split<<<dim3(16, 1024, 2), dim3(32, 8)>>>(anchor, ah, al, positive, ph, pl);
    split_w3<<<1280, 256>>>(W1, w1h, w1l, W2, w2h, w2l, Ww, wwh, wwl);

    // GEMM1: hidden = relu(a @ W1^T + b1)  [65536,512]
    mma_gemm<1><<<dim3(4, 512, 1), 256, SMEM_BYTES>>>(
        ah, al, 256, 0, w1h, w1l, 256, 0, 256,
        nullptr, 0, 0, hh, hl, 512, b1);
    // fused GEMM2+GEMM3: aprime in smem, pred -> g_a (anchor dead after residual)
    fused_mlp<<<1024, 256, F_SMEM_BYTES>>>(
        hh, hl, w2h, w2l, wwh, wwl, b2, ah, al, ah, al);
    // GEMM4 (batched over p=64): logits[p] = pred_p @ pos_p^T  [1024,1024]
    mma_gemm<0><<<dim3(8, 8, 64), 256, SMEM_BYTES>>>(
        ah, al, 16384, 256, ph, pl, 16384, 256, 256,
        out, 1024, 1048576, nullptr, nullptr, 0, nullptr);
    // subtract row max in-place
    rowmax_kernel<<<65536, 256>>>(out);
}

// round 13
// speedup vs baseline: 1.1644x; 1.1644x over previous
#include <cuda_runtime.h>
#include <cuda_bf16.h>
#include <cuda_fp16.h>

typedef __nv_bfloat16 bf16;

// ---------------------------------------------------------------------------
// StDimLocalLocalContrastModel via mma.sync (split emulated fp32).
//   P=64, B=1024, C=256, HID=512, M = B*P = 65536
// GEMM1-3: bf16 split-2, 3-MMA (err ~2^-18).
// GEMM4:   fp16 asymmetric 2-MMA (pred hi/lo x pos hi; err ~2^-12 ≈ 2e-4 rel).
// 3-stage cp.async, XOR swizzle, 2 CTAs/SM.
// ---------------------------------------------------------------------------

#define BM 128
#define BN 128
#define BKK 32
#define TILE_ELEMS 4096               // 128 rows x 32 elems (8 KB @2B)
#define NSTAGE 3
#define SMEM_BYTES  (4 * NSTAGE * TILE_ELEMS * 2)   // 96 KB (bf16 gemm)
#define SMEM4_BYTES (3 * NSTAGE * TILE_ELEMS * 2)   // 72 KB (gemm4)

// ---- scratch (device globals; allocation-free) ----
__device__ bf16   g_a_hi [16777216];  // [65536,256] anchor bf16 -> later pred fp16 (alias)
__device__ bf16   g_a_lo [16777216];
__device__ __half g_pos_h[16777216];  // [65536,256] positive fp16 (single)
__device__ bf16   g_hid_hi[33554432]; // [65536,512]
__device__ bf16   g_hid_lo[33554432];
__device__ bf16   g_ap_hi[16777216];  // [65536,256]
__device__ bf16   g_ap_lo[16777216];
__device__ bf16   g_w1_hi[131072], g_w1_lo[131072];  // [512,256]
__device__ bf16   g_w2_hi[131072], g_w2_lo[131072];  // [256,512]
__device__ bf16   g_ww_hi[65536],  g_ww_lo[65536];   // [256,256]

// ---- PTX helpers ----
__device__ __forceinline__ void cp16(const void* src, void* dst) {
    unsigned d = (unsigned)__cvta_generic_to_shared(dst);
    asm volatile("cp.async.cg.shared.global [%0], [%1], 16;" :: "r"(d), "l"(src));
}
__device__ __forceinline__ void cp_commit() { asm volatile("cp.async.commit_group;"); }
template<int N> __device__ __forceinline__ void cp_wait() {
    asm volatile("cp.async.wait_group %0;" :: "n"(N));
}
__device__ __forceinline__ void ldsm4(unsigned* r, const void* p) {
    unsigned a = (unsigned)__cvta_generic_to_shared(p);
    asm volatile("ldmatrix.sync.aligned.m8n8.x4.shared.b16 {%0,%1,%2,%3}, [%4];"
        : "=r"(r[0]), "=r"(r[1]), "=r"(r[2]), "=r"(r[3]) : "r"(a));
}
__device__ __forceinline__ void mma_bf16(float* d, const unsigned* a, const unsigned* b) {
    asm volatile(
        "mma.sync.aligned.m16n8k16.row.col.f32.bf16.bf16.f32 "
        "{%0,%1,%2,%3}, {%4,%5,%6,%7}, {%8,%9}, {%0,%1,%2,%3};"
        : "+f"(d[0]), "+f"(d[1]), "+f"(d[2]), "+f"(d[3])
        : "r"(a[0]), "r"(a[1]), "r"(a[2]), "r"(a[3]), "r"(b[0]), "r"(b[1]));
}
__device__ __forceinline__ void mma_f16(float* d, const unsigned* a, const unsigned* b) {
    asm volatile(
        "mma.sync.aligned.m16n8k16.row.col.f32.f16.f16.f32 "
        "{%0,%1,%2,%3}, {%4,%5,%6,%7}, {%8,%9}, {%0,%1,%2,%3};"
        : "+f"(d[0]), "+f"(d[1]), "+f"(d[2]), "+f"(d[3])
        : "r"(a[0]), "r"(a[1]), "r"(a[2]), "r"(a[3]), "r"(b[0]), "r"(b[1]));
}

// swizzle within a 128x32 (2-byte elem) tile: chunk' = chunk ^ ((row>>1)&3)
template<typename T>
__device__ __forceinline__ const T* swz(const T* tile, int row, int kcol) {
    return tile + row * 32 + ((((kcol >> 3)) ^ ((row >> 1) & 3)) << 3);
}

// ---------------------------------------------------------------------------
// mma_gemm (bf16 3-MMA): CTA 128x128, 3-stage, 2 CTAs/SM.
// MODE 1: relu(acc+bias)->bf16 hi/lo   MODE 2: acc+bias+resid->bf16 hi/lo
// MODE 3: plain->fp16 hi/lo (Ohi/Olo reinterpreted as __half*)
// ---------------------------------------------------------------------------
template<int MODE>
__global__ __launch_bounds__(256, 2)
void mma_gemm(const bf16* __restrict__ Ahi, const bf16* __restrict__ Alo, long As,
              const bf16* __restrict__ Bhi, const bf16* __restrict__ Blo, long Bs,
              int K,
              bf16* __restrict__ Ohi, bf16* __restrict__ Olo, long Os,
              const float* __restrict__ bias,
              const bf16* __restrict__ Rhi, const bf16* __restrict__ Rlo, long Rs)
{
    extern __shared__ bf16 smem[];
    bf16* sAh = smem;
    bf16* sAl = smem + NSTAGE * TILE_ELEMS;
    bf16* sBh = smem + 2 * NSTAGE * TILE_ELEMS;
    bf16* sBl = smem + 3 * NSTAGE * TILE_ELEMS;

    const int tid = threadIdx.x;
    const int wid = tid >> 5;
    const int lane = tid & 31;

    const bf16* gAh = Ahi + (long)blockIdx.y * BM * As;
    const bf16* gAl = Alo + (long)blockIdx.y * BM * As;
    const bf16* gBh = Bhi + (long)blockIdx.x * BN * Bs;
    const bf16* gBl = Blo + (long)blockIdx.x * BN * Bs;

    auto loadTile = [&](const bf16* g, long stride, int k0, bf16* dst) {
        #pragma unroll
        for (int it = 0; it < 2; it++) {
            int c = tid + it * 256;
            int r = c >> 2, kc = c & 3;
            cp16(g + (long)r * stride + k0 + kc * 8,
                 dst + r * 32 + ((kc ^ ((r >> 1) & 3)) << 3));
        }
    };
    auto loadAll = [&](int kt, int s) {
        int k0 = kt * BKK;
        loadTile(gAh, As, k0, sAh + s * TILE_ELEMS);
        loadTile(gAl, As, k0, sAl + s * TILE_ELEMS);
        loadTile(gBh, Bs, k0, sBh + s * TILE_ELEMS);
        loadTile(gBl, Bs, k0, sBl + s * TILE_ELEMS);
        cp_commit();
    };

    float acc[4][4][4];
    #pragma unroll
    for (int i = 0; i < 4; i++)
        #pragma unroll
        for (int j = 0; j < 4; j++)
            #pragma unroll
            for (int q = 0; q < 4; q++) acc[i][j][q] = 0.0f;

    const int wm = (wid >> 2) * 64;
    const int wn = (wid & 3) * 32;
    const int aRow = (lane & 7) + ((lane >> 3) & 1) * 8;
    const int aColH = ((lane >> 4) & 1) * 8;
    const int bRow = (lane & 7) + ((lane >> 4) & 1) * 8;
    const int bColH = ((lane >> 3) & 1) * 8;

    const int nk = K / BKK;
    loadAll(0, 0);
    loadAll(1, 1);

    for (int kt = 0; kt < nk; kt++) {
        if (kt + 1 < nk) cp_wait<1>(); else cp_wait<0>();
        __syncthreads();
        if (kt + 2 < nk) loadAll(kt + 2, (kt + 2) % NSTAGE);

        const int s = kt % NSTAGE;
        const bf16* Ah = sAh + s * TILE_ELEMS;
        const bf16* Al = sAl + s * TILE_ELEMS;
        const bf16* Bh = sBh + s * TILE_ELEMS;
        const bf16* Bl = sBl + s * TILE_ELEMS;

        #pragma unroll
        for (int kh = 0; kh < BKK; kh += 16) {
            unsigned Bh4[2][4], Bl4[2][4];
            #pragma unroll
            for (int nj = 0; nj < 2; nj++) {
                ldsm4(Bh4[nj], swz(Bh, wn + nj * 16 + bRow, kh + bColH));
                ldsm4(Bl4[nj], swz(Bl, wn + nj * 16 + bRow, kh + bColH));
            }
            #pragma unroll
            for (int mi = 0; mi < 4; mi++) {
                unsigned Ah4[4], Al4[4];
                ldsm4(Ah4, swz(Ah, wm + mi * 16 + aRow, kh + aColH));
                ldsm4(Al4, swz(Al, wm + mi * 16 + aRow, kh + aColH));
                #pragma unroll
                for (int ni = 0; ni < 4; ni++) {
                    const unsigned* bh = &Bh4[ni >> 1][(ni & 1) * 2];
                    const unsigned* bl = &Bl4[ni >> 1][(ni & 1) * 2];
                    mma_bf16(acc[mi][ni], Ah4, bh);
                    mma_bf16(acc[mi][ni], Ah4, bl);
                    mma_bf16(acc[mi][ni], Al4, bh);
                }
            }
        }
    }

    const int quad = lane >> 2, qt = lane & 3;
    const long rowBase = (long)blockIdx.y * BM + wm;
    const int colBase = blockIdx.x * BN + wn;

    #pragma unroll
    for (int mi = 0; mi < 4; mi++) {
        #pragma unroll
        for (int ni = 0; ni < 4; ni++) {
            #pragma unroll
            for (int half = 0; half < 2; half++) {
                long m = rowBase + mi * 16 + quad + half * 8;
                int n = colBase + ni * 8 + qt * 2;
                float v0 = acc[mi][ni][half * 2 + 0];
                float v1 = acc[mi][ni][half * 2 + 1];
                if (MODE == 1) {
                    v0 = fmaxf(v0 + bias[n], 0.0f);
                    v1 = fmaxf(v1 + bias[n + 1], 0.0f);
                } else if (MODE == 2) {
                    __nv_bfloat162 rh = *(const __nv_bfloat162*)(Rhi + m * Rs + n);
                    __nv_bfloat162 rl = *(const __nv_bfloat162*)(Rlo + m * Rs + n);
                    v0 += bias[n]     + __bfloat162float(rh.x) + __bfloat162float(rl.x);
                    v1 += bias[n + 1] + __bfloat162float(rh.y) + __bfloat162float(rl.y);
                }
                if (MODE == 3) {
                    __half* OH = (__half*)Ohi;
                    __half* OL = (__half*)Olo;
                    __half h0 = __float2half(v0);
                    __half h1 = __float2half(v1);
                    __half l0 = __float2half(v0 - __half2float(h0));
                    __half l1 = __float2half(v1 - __half2float(h1));
                    *(__half2*)(OH + m * Os + n) = __halves2half2(h0, h1);
                    *(__half2*)(OL + m * Os + n) = __halves2half2(l0, l1);
                } else {
                    bf16 h0 = __float2bfloat16(v0);
                    bf16 h1 = __float2bfloat16(v1);
                    bf16 l0 = __float2bfloat16(v0 - __bfloat162float(h0));
                    bf16 l1 = __float2bfloat16(v1 - __bfloat162float(h1));
                    __nv_bfloat162 hp; hp.x = h0; hp.y = h1;
                    __nv_bfloat162 lp; lp.x = l0; lp.y = l1;
                    *(__nv_bfloat162*)(Ohi + m * Os + n) = hp;
                    *(__nv_bfloat162*)(Olo + m * Os + n) = lp;
                }
            }
        }
    }
}

// ---------------------------------------------------------------------------
// gemm4_f16: logits[p] = pred_p @ pos_p^T, fp16 asymmetric 2-MMA.
// A = pred hi/lo fp16, B = pos fp16 single.  Row stride 16384, batch off p*256.
// ---------------------------------------------------------------------------
__global__ __launch_bounds__(256, 2)
void gemm4_f16(const __half* __restrict__ Ah_, const __half* __restrict__ Al_,
               const __half* __restrict__ Bh_, float* __restrict__ Cf)
{
    extern __shared__ __half hsm[];
    __half* sAh = hsm;
    __half* sAl = hsm + NSTAGE * TILE_ELEMS;
    __half* sBh = hsm + 2 * NSTAGE * TILE_ELEMS;

    const int tid = threadIdx.x;
    const int wid = tid >> 5;
    const int lane = tid & 31;
    const long z = blockIdx.z;

    const __half* gAh = Ah_ + z * 256 + (long)blockIdx.y * BM * 16384;
    const __half* gAl = Al_ + z * 256 + (long)blockIdx.y * BM * 16384;
    const __half* gBh = Bh_ + z * 256 + (long)blockIdx.x * BN * 16384;

    auto loadTile = [&](const __half* g, int k0, __half* dst) {
        #pragma unroll
        for (int it = 0; it < 2; it++) {
            int c = tid + it * 256;
            int r = c >> 2, kc = c & 3;
            cp16(g + (long)r * 16384 + k0 + kc * 8,
                 dst + r * 32 + ((kc ^ ((r >> 1) & 3)) << 3));
        }
    };
    auto loadAll = [&](int kt, int s) {
        int k0 = kt * BKK;
        loadTile(gAh, k0, sAh + s * TILE_ELEMS);
        loadTile(gAl, k0, sAl + s * TILE_ELEMS);
        loadTile(gBh, k0, sBh + s * TILE_ELEMS);
        cp_commit();
    };

    float acc[4][4][4];
    #pragma unroll
    for (int i = 0; i < 4; i++)
        #pragma unroll
        for (int j = 0; j < 4; j++)
            #pragma unroll
            for (int q = 0; q < 4; q++) acc[i][j][q] = 0.0f;

    const int wm = (wid >> 2) * 64;
    const int wn = (wid & 3) * 32;
    const int aRow = (lane & 7) + ((lane >> 3) & 1) * 8;
    const int aColH = ((lane >> 4) & 1) * 8;
    const int bRow = (lane & 7) + ((lane >> 4) & 1) * 8;
    const int bColH = ((lane >> 3) & 1) * 8;

    const int nk = 256 / BKK;   // 8
    loadAll(0, 0);
    loadAll(1, 1);

    for (int kt = 0; kt < nk; kt++) {
        if (kt + 1 < nk) cp_wait<1>(); else cp_wait<0>();
        __syncthreads();
        if (kt + 2 < nk) loadAll(kt + 2, (kt + 2) % NSTAGE);

        const int s = kt % NSTAGE;
        const __half* Ah = sAh + s * TILE_ELEMS;
        const __half* Al = sAl + s * TILE_ELEMS;
        const __half* Bh = sBh + s * TILE_ELEMS;

        #pragma unroll
        for (int kh = 0; kh < BKK; kh += 16) {
            unsigned Bh4[2][4];
            #pragma unroll
            for (int nj = 0; nj < 2; nj++)
                ldsm4(Bh4[nj], swz(Bh, wn + nj * 16 + bRow, kh + bColH));
            #pragma unroll
            for (int mi = 0; mi < 4; mi++) {
                unsigned Ah4[4], Al4[4];
                ldsm4(Ah4, swz(Ah, wm + mi * 16 + aRow, kh + aColH));
                ldsm4(Al4, swz(Al, wm + mi * 16 + aRow, kh + aColH));
                #pragma unroll
                for (int ni = 0; ni < 4; ni++) {
                    const unsigned* bh = &Bh4[ni >> 1][(ni & 1) * 2];
                    mma_f16(acc[mi][ni], Ah4, bh);   // hi*hi
                    mma_f16(acc[mi][ni], Al4, bh);   // lo*hi (A-side split)
                }
            }
        }
    }

    const int quad = lane >> 2, qt = lane & 3;
    const long rowBase = (long)blockIdx.y * BM + wm;
    const int colBase = blockIdx.x * BN + wn;
    float* Cz = Cf + z * 1048576;

    #pragma unroll
    for (int mi = 0; mi < 4; mi++) {
        #pragma unroll
        for (int ni = 0; ni < 4; ni++) {
            #pragma unroll
            for (int half = 0; half < 2; half++) {
                long m = rowBase + mi * 16 + quad + half * 8;
                int n = colBase + ni * 8 + qt * 2;
                *(float2*)(Cz + m * 1024 + n) =
                    make_float2(acc[mi][ni][half * 2 + 0], acc[mi][ni][half * 2 + 1]);
            }
        }
    }
}

// ---------------------------------------------------------------------------
// prep: z=0 anchor -> bf16 hi/lo; z=1 positive -> fp16 single
// ---------------------------------------------------------------------------
__global__ void transpose_split(const float* __restrict__ in0, bf16* __restrict__ h0, bf16* __restrict__ l0,
                                const float* __restrict__ in1, __half* __restrict__ h1) {
    __shared__ float t[32][33];
    int zz = blockIdx.z;
    const float* in = zz ? in1 : in0;
    int b  = blockIdx.y;
    int c0 = (blockIdx.x & 7) * 32;
    int p0 = (blockIdx.x >> 3) * 32;
    const float* src = in + (long)b * 16384;
    #pragma unroll
    for (int j = 0; j < 32; j += 8)
        t[threadIdx.y + j][threadIdx.x] = src[(c0 + threadIdx.y + j) * 64 + p0 + threadIdx.x];
    __syncthreads();
    #pragma unroll
    for (int j = 0; j < 32; j += 8) {
        float v = t[threadIdx.x][threadIdx.y + j];
        long rowoff = ((long)b * 64 + p0 + threadIdx.y + j) * 256 + c0 + threadIdx.x;
        if (zz == 0) {
            bf16 h = __float2bfloat16(v);
            h0[rowoff] = h;
            l0[rowoff] = __float2bfloat16(v - __bfloat162float(h));
        } else {
            h1[rowoff] = __float2half(v);
        }
    }
}

// all three weight splits: W1 (131072) | W2 (131072) | Ww (65536)
__global__ void split_w3(const float* __restrict__ W1, bf16* __restrict__ w1h, bf16* __restrict__ w1l,
                         const float* __restrict__ W2, bf16* __restrict__ w2h, bf16* __restrict__ w2l,
                         const float* __restrict__ Ww, bf16* __restrict__ wwh, bf16* __restrict__ wwl) {
    int i = blockIdx.x * 256 + threadIdx.x;
    const float* w; bf16 *hi, *lo; int off;
    if (i < 131072)      { w = W1; hi = w1h; lo = w1l; off = i; }
    else if (i < 262144) { w = W2; hi = w2h; lo = w2l; off = i - 131072; }
    else                 { w = Ww; hi = wwh; lo = wwl; off = i - 262144; }
    float v = w[off];
    bf16 h = __float2bfloat16(v);
    hi[off] = h;
    lo[off] = __float2bfloat16(v - __bfloat162float(h));
}

// subtract row max in-place, row = 1024 floats
__global__ void rowmax_kernel(float* __restrict__ out) {
    long row = blockIdx.x;
    float4* rp = (float4*)(out + row * 1024);
    float4 v = rp[threadIdx.x];
    float m = fmaxf(fmaxf(v.x, v.y), fmaxf(v.z, v.w));
    #pragma unroll
    for (int o = 16; o; o >>= 1) m = fmaxf(m, __shfl_xor_sync(0xffffffffu, m, o));
    __shared__ float sm[8];
    if ((threadIdx.x & 31) == 0) sm[threadIdx.x >> 5] = m;
    __syncthreads();
    float mm = sm[0];
    #pragma unroll
    for (int i = 1; i < 8; i++) mm = fmaxf(mm, sm[i]);
    v.x -= mm; v.y -= mm; v.z -= mm; v.w -= mm;
    rp[threadIdx.x] = v;
}

extern "C" void kernel_launch(void* const* d_in, const int* in_sizes, int n_in,
                              void* d_out, int out_size) {
    const float* anchor   = (const float*)d_in[0];
    const float* positive = (const float*)d_in[1];
    const float* W1 = (const float*)d_in[2];
    const float* b1 = (const float*)d_in[3];
    const float* W2 = (const float*)d_in[4];
    const float* b2 = (const float*)d_in[5];
    const float* Ww = (const float*)d_in[6];
    float* out = (float*)d_out;

    bf16 *ah, *al, *hh, *hl, *aph, *apl;
    bf16 *w1h, *w1l, *w2h, *w2l, *wwh, *wwl;
    __half* posh;
    cudaGetSymbolAddress((void**)&ah,   g_a_hi);
    cudaGetSymbolAddress((void**)&al,   g_a_lo);
    cudaGetSymbolAddress((void**)&posh, g_pos_h);
    cudaGetSymbolAddress((void**)&hh,   g_hid_hi);
    cudaGetSymbolAddress((void**)&hl,   g_hid_lo);
    cudaGetSymbolAddress((void**)&aph,  g_ap_hi);
    cudaGetSymbolAddress((void**)&apl,  g_ap_lo);
    cudaGetSymbolAddress((void**)&w1h,  g_w1_hi);
    cudaGetSymbolAddress((void**)&w1l,  g_w1_lo);
    cudaGetSymbolAddress((void**)&w2h,  g_w2_hi);
    cudaGetSymbolAddress((void**)&w2l,  g_w2_lo);
    cudaGetSymbolAddress((void**)&wwh,  g_ww_hi);
    cudaGetSymbolAddress((void**)&wwl,  g_ww_lo);

    cudaFuncSetAttribute(mma_gemm<1>, cudaFuncAttributeMaxDynamicSharedMemorySize, SMEM_BYTES);
    cudaFuncSetAttribute(mma_gemm<2>, cudaFuncAttributeMaxDynamicSharedMemorySize, SMEM_BYTES);
    cudaFuncSetAttribute(mma_gemm<3>, cudaFuncAttributeMaxDynamicSharedMemorySize, SMEM_BYTES);
    cudaFuncSetAttribute(gemm4_f16,   cudaFuncAttributeMaxDynamicSharedMemorySize, SMEM4_BYTES);

    // prep
    transpose_split<<<dim3(16, 1024, 2), dim3(32, 8)>>>(anchor, ah, al, positive, posh);
    split_w3<<<1280, 256>>>(W1, w1h, w1l, W2, w2h, w2l, Ww, wwh, wwl);

    // GEMM1: hidden = relu(a @ W1^T + b1)  [65536,512]
    mma_gemm<1><<<dim3(4, 512), 256, SMEM_BYTES>>>(
        ah, al, 256, w1h, w1l, 256, 256, hh, hl, 512, b1, nullptr, nullptr, 0);
    // GEMM2: aprime = a + hidden @ W2^T + b2  [65536,256]
    mma_gemm<2><<<dim3(2, 512), 256, SMEM_BYTES>>>(
        hh, hl, 512, w2h, w2l, 512, 512, aph, apl, 256, b2, ah, al, 256);
    // GEMM3: pred = aprime @ Ww^T -> fp16 hi/lo over dead anchor buffers
    mma_gemm<3><<<dim3(2, 512), 256, SMEM_BYTES>>>(
        aph, apl, 256, wwh, wwl, 256, 256, ah, al, 256, nullptr, nullptr, nullptr, 0);
    // GEMM4 (batched p=64): logits[p] = pred_p @ pos_p^T, fp16 2-MMA
    gemm4_f16<<<dim3(8, 8, 64), 256, SMEM4_BYTES>>>(
        (const __half*)ah, (const __half*)al, posh, out);
    // subtract row max in-place
    rowmax_kernel<<<65536, 256>>>(out);
}